// round 9
// baseline (speedup 1.0000x reference)
#include <cuda_runtime.h>

// Problem constants (fixed by the reference: H=512, N=64, CH=1, L=2048)
#define HH   512
#define NST  64
#define LFFT 2048
#define NF   1024      // half-size complex IFFT length
#define NTH  128       // cauchy block size
#define FTH  256       // fft block size
#define JILP 4         // l-bins per thread
#define LCHUNK (NTH * JILP)       // 512 l-bins per cauchy block
#define NCHUNK (LFFT / LCHUNK)    // 4 blocks per head

typedef unsigned long long ull;

// K_hat scratch: 512 heads x 2048 bins x complex64 = 8 MB (static, no allocation)
__device__ float2 g_khat[HH * LFFT];

__device__ __forceinline__ ull pack2(float a, float b) {
    ull r;
    asm("mov.b64 %0, {%1, %2};" : "=l"(r) : "f"(a), "f"(b));
    return r;
}
__device__ __forceinline__ void unpack2(ull v, float& a, float& b) {
    asm("mov.b64 {%0, %1}, %2;" : "=f"(a), "=f"(b) : "l"(v));
}
__device__ __forceinline__ ull ffma2(ull a, ull b, ull c) {
    ull d;
    asm("fma.rn.f32x2 %0, %1, %2, %3;" : "=l"(d) : "l"(a), "l"(b), "l"(c));
    return d;
}
__device__ __forceinline__ float frcp(float x) {
    float r;
    asm("rcp.approx.f32 %0, %1;" : "=f"(r) : "f"(x));
    return r;
}

// ============================================================================
// Kernel 1: Cauchy + Woodbury -> K_hat.
// grid = HH * NCHUNK (2048), block = 128, each thread owns JILP=4 bins:
//   l = chunk*512 + j*128 + tid
// Two-pack complex accumulation (j-inner, q/p transient):
//   acc=(re,im): ffma2((cr*dr, -cr), q=(s,ds)); ffma2((ci, ci*dr), p=(ds,s))
//   PRP (real v): ffma2((v*dr, -v), q)
// ============================================================================
__global__ void __launch_bounds__(NTH, 6)
cauchy_kernel(const float* __restrict__ lam_re_in, const float* __restrict__ lam_im_in,
              const float* __restrict__ p_re,  const float* __restrict__ p_im,
              const float* __restrict__ b_re,  const float* __restrict__ b_im,
              const float* __restrict__ c_re,  const float* __restrict__ c_im,
              const float* __restrict__ log_dt)
{
    // Pre-packed f32x2 operand quads per n (64B):
    //   [0] = { (ur*dr, -ur), (ui, ui*dr) }    u = conj(P)*B
    //   [1] = { (wr*dr, -wr), (wi, wi*dr) }    w = conj(C)*B
    //   [2] = { (xr*dr, -xr), (xi, xi*dr) }    x = conj(C)*P
    //   [3] = { (v*dr,  -v),  (dr2, lam)  }    v = |P|^2
    __shared__ ulonglong2 cst[NST * 4];
    __shared__ float4 rA[NST];      // raw (lam_re, ur, ui, v)  for l==1024 fixup
    __shared__ float4 rB[NST];      // raw (wr, wi, xr, xi)

    const int h     = blockIdx.x / NCHUNK;
    const int chunk = blockIdx.x % NCHUNK;
    const int tid   = threadIdx.x;
    const int lbase = chunk * LCHUNK;

    if (tid < NST) {
        const int idx = h * NST + tid;
        float lr = -log1pf(expf(lam_re_in[idx]));   // Lambda_re = -softplus
        float li = lam_im_in[idx];
        float pr = p_re[idx], pi = p_im[idx];
        float br = b_re[idx], bi = b_im[idx];
        float cr = c_re[idx], ci = c_im[idx];
        float ur = pr * br + pi * bi;
        float ui = pr * bi - pi * br;
        float v  = pr * pr + pi * pi;
        float wr = cr * br + ci * bi;
        float wi = cr * bi - ci * br;
        float xr = cr * pr + ci * pi;
        float xi = cr * pi - ci * pr;
        float dr = -lr;                 // g purely imaginary -> dr l-invariant
        cst[tid * 4 + 0] = make_ulonglong2(pack2(ur * dr, -ur), pack2(ui, ui * dr));
        cst[tid * 4 + 1] = make_ulonglong2(pack2(wr * dr, -wr), pack2(wi, wi * dr));
        cst[tid * 4 + 2] = make_ulonglong2(pack2(xr * dr, -xr), pack2(xi, xi * dr));
        cst[tid * 4 + 3] = make_ulonglong2(pack2(v * dr,  -v),  pack2(dr * dr, li));
        rA[tid] = make_float4(lr, ur, ui, v);
        rB[tid] = make_float4(wr, wi, xr, xi);
    }
    const float tdt = 2.0f * expf(-log_dt[h]);    // 2/dt
    __syncthreads();

    float gi[JILP];
#pragma unroll
    for (int j = 0; j < JILP; j++) {
        const int l = lbase + j * NTH + tid;
        float sp, cp;
        sincospif(l * (1.0f / 2048.0f), &sp, &cp);   // theta/2 = pi*l/2048
        gi[j] = tdt * __fdividef(sp, cp);            // g = i * (2/dt) tan(theta/2)
    }
    ull aU[JILP], aW[JILP], aX[JILP], aV[JILP];
#pragma unroll
    for (int j = 0; j < JILP; j++)
        aU[j] = aW[j] = aX[j] = aV[j] = 0ull;

#pragma unroll 2
    for (int n = 0; n < NST; n++) {
        const ulonglong2 t0 = cst[4 * n + 0];
        const ulonglong2 t1 = cst[4 * n + 1];
        const ulonglong2 t2 = cst[4 * n + 2];
        const ulonglong2 t3 = cst[4 * n + 3];
        float dr2, lam;
        unpack2(t3.y, dr2, lam);
#pragma unroll
        for (int j = 0; j < JILP; j++) {
            const float di = gi[j] - lam;
            const float s  = frcp(fmaf(di, di, dr2));
            const float ds = di * s;
            const ull q = pack2(s, ds);
            const ull p = pack2(ds, s);
            aU[j] = ffma2(t0.x, q, aU[j]);
            aU[j] = ffma2(t0.y, p, aU[j]);
            aW[j] = ffma2(t1.x, q, aW[j]);
            aW[j] = ffma2(t1.y, p, aW[j]);
            aX[j] = ffma2(t2.x, q, aX[j]);
            aX[j] = ffma2(t2.y, p, aX[j]);
            aV[j] = ffma2(t3.x, q, aV[j]);
        }
    }

#pragma unroll
    for (int j = 0; j < JILP; j++) {
        float PRBr, PRBi, CRBr, CRBi, CRPr, CRPi, PRPr, PRPi;
        unpack2(aU[j], PRBr, PRBi);
        unpack2(aW[j], CRBr, CRBi);
        unpack2(aX[j], CRPr, CRPi);
        unpack2(aV[j], PRPr, PRPi);
        const float wr_ = 1.0f + PRPr, wi_ = PRPi;
        const float invW = frcp(fmaf(wr_, wr_, wi_ * wi_));
        const float fr = (PRBr * wr_ + PRBi * wi_) * invW;
        const float fi = (PRBi * wr_ - PRBr * wi_) * invW;
        const float er = CRBr - (CRPr * fr - CRPi * fi);
        const float ei = CRBi - (CRPr * fi + CRPi * fr);
        const int l = lbase + j * NTH + tid;
        // recompute tau here (keeps it out of the mainloop register set)
        float sp, cp;
        sincospif(l * (1.0f / 2048.0f), &sp, &cp);
        const float tau = __fdividef(sp, cp);
        // K_hat = (1 + i*tau) * e
        g_khat[h * LFFT + l] = make_float2(er - tau * ei, ei + tau * er);
    }

    // l == 1024 fixup (z = -1, eps-clamped bin) — chunk 2, tid 0 wrote the NaN
    // bin above (j=0), so this overwrite is same-thread ordered.
    if (chunk == 2 && tid == 0) {
        const float EPS = 1.1920929e-7f;
        const float gr = tdt * (2.0f / EPS);   // g real
        float PRBr = 0.f, PRBi = 0.f, PRPr = 0.f, PRPi = 0.f;
        float CRBr = 0.f, CRBi = 0.f, CRPr = 0.f, CRPi = 0.f;
        for (int n = 0; n < NST; n++) {
            const float4 a = rA[n];
            const float4 b = rB[n];
            float dr2_, lim;
            unpack2(cst[4 * n + 3].y, dr2_, lim);
            const float dr = gr - a.x;
            const float di = -lim;
            const float rinv = 1.0f / fmaf(dr, dr, di * di);
            const float Rr =  dr * rinv;
            const float Ri = -di * rinv;
            PRBr = fmaf(a.y, Rr, PRBr); PRBr = fmaf(-a.z, Ri, PRBr);
            PRBi = fmaf(a.y, Ri, PRBi); PRBi = fmaf( a.z, Rr, PRBi);
            PRPr = fmaf(a.w, Rr, PRPr);
            PRPi = fmaf(a.w, Ri, PRPi);
            CRBr = fmaf(b.x, Rr, CRBr); CRBr = fmaf(-b.y, Ri, CRBr);
            CRBi = fmaf(b.x, Ri, CRBi); CRBi = fmaf( b.y, Rr, CRBi);
            CRPr = fmaf(b.z, Rr, CRPr); CRPr = fmaf(-b.w, Ri, CRPr);
            CRPi = fmaf(b.z, Ri, CRPi); CRPi = fmaf( b.w, Rr, CRPi);
        }
        const float wr_ = 1.0f + PRPr, wi_ = PRPi;
        const float invW = 1.0f / fmaf(wr_, wr_, wi_ * wi_);
        const float fr = (PRBr * wr_ + PRBi * wi_) * invW;
        const float fi = (PRBi * wr_ - PRBr * wi_) * invW;
        const float er = CRBr - (CRPr * fr - CRPi * fi);
        const float ei = CRBi - (CRPr * fi + CRPi * fr);
        const float t2 = 2.0f / EPS;
        g_khat[h * LFFT + 1024] = make_float2(t2 * er, t2 * ei);
    }
}

// ============================================================================
// Kernel 2: Hermitian fold + 1024-pt C2R inverse FFT + store.  grid = HH.
// ============================================================================
__global__ void __launch_bounds__(FTH)
fft_kernel(const float* __restrict__ d_in, float* __restrict__ out, int write_d)
{
    __shared__ float2 Kh[LFFT];     // loaded spectrum; reused as FFT pong
    __shared__ float2 Cb[NF];       // folded C2R spectrum / FFT ping
    __shared__ float2 tw[NF / 2];   // IFFT-1024 twiddles e^{+2*pi*i*j/1024}

    const int h   = blockIdx.x;
    const int tid = threadIdx.x;

    // vectorized spectrum load (1024 float4s, 4 iters, high MLP)
    {
        const float4* src = (const float4*)(g_khat + h * LFFT);
        float4* dst = (float4*)Kh;
#pragma unroll
        for (int t = 0; t < LFFT / 2 / FTH; t++)
            dst[t * FTH + tid] = src[t * FTH + tid];
    }
    for (int j = tid; j < NF / 2; j += FTH) {
        float s, c;
        sincospif(j * (1.0f / 512.0f), &s, &c);
        tw[j] = make_float2(c, s);
    }
    __syncthreads();

    // Fold: Re(ifft2048(X)) == ifft1024(C) interleaved as (x[2n], x[2n+1])
    for (int k = tid; k < NF; k += FTH) {
        const float2 P  = Kh[k];
        const float2 Qv = Kh[(2048 - k) & 2047];
        const float2 Rv = Kh[1024 - k];
        const float2 Sv = Kh[1024 + k];
        const float Er = (P.x + Qv.x + Rv.x + Sv.x) * 0.25f;
        const float Ei = (P.y - Qv.y - Rv.y + Sv.y) * 0.25f;
        const float Dr = (P.x + Qv.x - Rv.x - Sv.x) * 0.25f;
        const float Di = (P.y - Qv.y + Rv.y - Sv.y) * 0.25f;
        float st, ct;
        sincospif(k * (1.0f / 1024.0f), &st, &ct);
        const float Or = -st * Dr - ct * Di;
        const float Oi =  ct * Dr - st * Di;
        Cb[k] = make_float2(Er + Or, Ei + Oi);
    }

    // 1024-point Stockham radix-2 inverse FFT
    {
        float2* Abuf = Cb;
        float2* Bbuf = Kh;
        int s = 1;
        for (int ncur = NF; ncur >= 4; ncur >>= 1, s <<= 1) {   // 9 stages
            __syncthreads();
#pragma unroll 2
            for (int kk = 0; kk < 2; kk++) {
                const int bi    = tid + kk * FTH;        // [0, 512)
                const int pbase = bi & ~(s - 1);
                const float2 a = Abuf[bi];
                const float2 b = Abuf[bi + NF / 2];
                const float2 w = tw[pbase];
                const int o = bi + pbase;
                Bbuf[o] = make_float2(a.x + b.x, a.y + b.y);
                const float sr = a.x - b.x, si = a.y - b.y;
                Bbuf[o + s] = make_float2(sr * w.x - si * w.y, sr * w.y + si * w.x);
            }
            float2* tmp = Abuf; Abuf = Bbuf; Bbuf = tmp;
        }
        __syncthreads();
#pragma unroll 2
        for (int kk = 0; kk < 2; kk++) {
            const int bi = tid + kk * FTH;
            const float2 a = Abuf[bi];
            const float2 b = Abuf[bi + NF / 2];
            Abuf[bi]          = make_float2(a.x + b.x, a.y + b.y);
            Abuf[bi + NF / 2] = make_float2(a.x - b.x, a.y - b.y);
        }
        __syncthreads();

        const float sc = 1.0f / (float)NF;
        float2* o2 = (float2*)out;
        for (int n2 = tid; n2 < NF; n2 += FTH) {
            const float2 cv = Abuf[n2];
            o2[h * NF + n2] = make_float2(cv.x * sc, cv.y * sc);
        }
    }

    if (write_d && tid == 0)
        out[HH * LFFT + h] = d_in[h];
}

extern "C" void kernel_launch(void* const* d_in, const int* in_sizes, int n_in,
                              void* d_out, int out_size)
{
    const float* lam_re = (const float*)d_in[0];
    const float* lam_im = (const float*)d_in[1];
    const float* p_re   = (const float*)d_in[2];
    const float* p_im   = (const float*)d_in[3];
    const float* b_re   = (const float*)d_in[4];
    const float* b_im   = (const float*)d_in[5];
    const float* c_re   = (const float*)d_in[6];
    const float* c_im   = (const float*)d_in[7];
    const float* Dv     = (const float*)d_in[8];
    const float* log_dt = (const float*)d_in[9];
    float* out = (float*)d_out;

    const int write_d = (out_size >= HH * LFFT + HH) ? 1 : 0;

    cauchy_kernel<<<HH * NCHUNK, NTH>>>(lam_re, lam_im, p_re, p_im,
                                        b_re, b_im, c_re, c_im, log_dt);
    fft_kernel<<<HH, FTH>>>(Dv, out, write_d);
}

// round 10
// speedup vs baseline: 1.1396x; 1.1396x over previous
#include <cuda_runtime.h>

// Problem constants (fixed by the reference: H=512, N=64, CH=1, L=2048)
#define HH   512
#define NST  64
#define LFFT 2048
#define NF   1024      // half-size complex IFFT length
#define NTH  256       // cauchy block size
#define FTH  256       // fft block size
#define LCHUNK 1024    // l-bins per cauchy block
#define NCHUNK (LFFT / LCHUNK)   // 2 blocks per head
#define JILP 4         // l-bins per thread

typedef unsigned long long ull;

// K_hat scratch: 512 heads x 2048 bins x complex64 = 8 MB (static, no allocation)
__device__ float2 g_khat[HH * LFFT];

__device__ __forceinline__ ull pack2(float a, float b) {
    ull r;
    asm("mov.b64 %0, {%1, %2};" : "=l"(r) : "f"(a), "f"(b));
    return r;
}
__device__ __forceinline__ void unpack2(ull v, float& a, float& b) {
    asm("mov.b64 {%0, %1}, %2;" : "=f"(a), "=f"(b) : "l"(v));
}
__device__ __forceinline__ ull ffma2(ull a, ull b, ull c) {
    ull d;
    asm("fma.rn.f32x2 %0, %1, %2, %3;" : "=l"(d) : "l"(a), "l"(b), "l"(c));
    return d;
}
__device__ __forceinline__ float frcp(float x) {
    float r;
    asm("rcp.approx.f32 %0, %1;" : "=f"(r) : "f"(x));
    return r;
}

// ============================================================================
// Kernel 1 (R6-proven form): Cauchy + Woodbury -> K_hat.
// grid = HH * NCHUNK (1024), block = 256, each thread owns JILP=4 bins:
//   l = chunk*1024 + j*256 + tid
// ============================================================================
__global__ void __launch_bounds__(NTH, 3)
cauchy_kernel(const float* __restrict__ lam_re_in, const float* __restrict__ lam_im_in,
              const float* __restrict__ p_re,  const float* __restrict__ p_im,
              const float* __restrict__ b_re,  const float* __restrict__ b_im,
              const float* __restrict__ c_re,  const float* __restrict__ c_im,
              const float* __restrict__ log_dt)
{
    // Pre-packed f32x2 operand quads per n (64B):
    //   [0] = { (ur*dr, ui*dr),  (ui, -ur) }    u = conj(P)*B
    //   [1] = { (wr*dr, wi*dr),  (wi, -wr) }    w = conj(C)*B
    //   [2] = { (xr*dr, xi*dr),  (xi, -xr) }    x = conj(C)*P
    //   [3] = { (v*dr, -v),      (dr2, lam) }   v = |P|^2
    __shared__ ulonglong2 cst[NST * 4];
    __shared__ float4 rA[NST];      // raw (lam_re, ur, ui, v)  for l==1024 fixup
    __shared__ float4 rB[NST];      // raw (wr, wi, xr, xi)

    const int h     = blockIdx.x / NCHUNK;
    const int chunk = blockIdx.x % NCHUNK;
    const int tid   = threadIdx.x;
    const int lbase = chunk * LCHUNK;

    if (tid < NST) {
        const int idx = h * NST + tid;
        float lr = -log1pf(expf(lam_re_in[idx]));   // Lambda_re = -softplus
        float li = lam_im_in[idx];
        float pr = p_re[idx], pi = p_im[idx];
        float br = b_re[idx], bi = b_im[idx];
        float cr = c_re[idx], ci = c_im[idx];
        float ur = pr * br + pi * bi;
        float ui = pr * bi - pi * br;
        float v  = pr * pr + pi * pi;
        float wr = cr * br + ci * bi;
        float wi = cr * bi - ci * br;
        float xr = cr * pr + ci * pi;
        float xi = cr * pi - ci * pr;
        float dr = -lr;                 // g purely imaginary -> dr l-invariant
        cst[tid * 4 + 0] = make_ulonglong2(pack2(ur * dr, ui * dr), pack2(ui, -ur));
        cst[tid * 4 + 1] = make_ulonglong2(pack2(wr * dr, wi * dr), pack2(wi, -wr));
        cst[tid * 4 + 2] = make_ulonglong2(pack2(xr * dr, xi * dr), pack2(xi, -xr));
        cst[tid * 4 + 3] = make_ulonglong2(pack2(v * dr, -v),       pack2(dr * dr, li));
        rA[tid] = make_float4(lr, ur, ui, v);
        rB[tid] = make_float4(wr, wi, xr, xi);
    }
    const float tdt = 2.0f * expf(-log_dt[h]);    // 2/dt
    __syncthreads();

    float gi[JILP], tau[JILP];
#pragma unroll
    for (int j = 0; j < JILP; j++) {
        const int l = lbase + j * NTH + tid;
        float sp, cp;
        sincospif(l * (1.0f / 2048.0f), &sp, &cp);   // theta/2 = pi*l/2048
        tau[j] = __fdividef(sp, cp);                 // tan(theta/2)
        gi[j]  = tdt * tau[j];                       // g = i*gi
    }
    ull aU[JILP], aW[JILP], aX[JILP], aV[JILP];
#pragma unroll
    for (int j = 0; j < JILP; j++)
        aU[j] = aW[j] = aX[j] = aV[j] = 0ull;

#pragma unroll 4
    for (int n = 0; n < NST; n++) {
        const ulonglong2 t0 = cst[4 * n + 0];
        const ulonglong2 t1 = cst[4 * n + 1];
        const ulonglong2 t2 = cst[4 * n + 2];
        const ulonglong2 t3 = cst[4 * n + 3];
        float dr2, lam;
        unpack2(t3.y, dr2, lam);
#pragma unroll
        for (int j = 0; j < JILP; j++) {
            const float di = gi[j] - lam;
            const float s  = frcp(fmaf(di, di, dr2));
            const float ds = di * s;
            const ull s2  = pack2(s, s);
            const ull ds2 = pack2(ds, ds);
            const ull q   = pack2(s, ds);
            aU[j] = ffma2(t0.x, s2,  aU[j]);
            aU[j] = ffma2(t0.y, ds2, aU[j]);
            aW[j] = ffma2(t1.x, s2,  aW[j]);
            aW[j] = ffma2(t1.y, ds2, aW[j]);
            aX[j] = ffma2(t2.x, s2,  aX[j]);
            aX[j] = ffma2(t2.y, ds2, aX[j]);
            aV[j] = ffma2(t3.x, q,   aV[j]);
        }
    }
#pragma unroll
    for (int j = 0; j < JILP; j++) {
        float PRBr, PRBi, CRBr, CRBi, CRPr, CRPi, PRPr, PRPi;
        unpack2(aU[j], PRBr, PRBi);
        unpack2(aW[j], CRBr, CRBi);
        unpack2(aX[j], CRPr, CRPi);
        unpack2(aV[j], PRPr, PRPi);
        const float wr_ = 1.0f + PRPr, wi_ = PRPi;
        const float invW = frcp(fmaf(wr_, wr_, wi_ * wi_));
        const float fr = (PRBr * wr_ + PRBi * wi_) * invW;
        const float fi = (PRBi * wr_ - PRBr * wi_) * invW;
        const float er = CRBr - (CRPr * fr - CRPi * fi);
        const float ei = CRBi - (CRPr * fi + CRPi * fr);
        const int l = lbase + j * NTH + tid;
        // K_hat = (1 + i*tau) * e
        g_khat[h * LFFT + l] = make_float2(er - tau[j] * ei, ei + tau[j] * er);
    }

    // l == 1024 fixup (z = -1, eps-clamped bin) — chunk 1, tid 0 wrote the NaN
    // bin above (j=0), so this overwrite is same-thread ordered.
    if (chunk == 1 && tid == 0) {
        const float EPS = 1.1920929e-7f;
        const float gr = tdt * (2.0f / EPS);   // g real
        float PRBr = 0.f, PRBi = 0.f, PRPr = 0.f, PRPi = 0.f;
        float CRBr = 0.f, CRBi = 0.f, CRPr = 0.f, CRPi = 0.f;
        for (int n = 0; n < NST; n++) {
            const float4 a = rA[n];
            const float4 b = rB[n];
            float dr2_, lim;
            unpack2(cst[4 * n + 3].y, dr2_, lim);
            const float dr = gr - a.x;
            const float di = -lim;
            const float rinv = 1.0f / fmaf(dr, dr, di * di);
            const float Rr =  dr * rinv;
            const float Ri = -di * rinv;
            PRBr = fmaf(a.y, Rr, PRBr); PRBr = fmaf(-a.z, Ri, PRBr);
            PRBi = fmaf(a.y, Ri, PRBi); PRBi = fmaf( a.z, Rr, PRBi);
            PRPr = fmaf(a.w, Rr, PRPr);
            PRPi = fmaf(a.w, Ri, PRPi);
            CRBr = fmaf(b.x, Rr, CRBr); CRBr = fmaf(-b.y, Ri, CRBr);
            CRBi = fmaf(b.x, Ri, CRBi); CRBi = fmaf( b.y, Rr, CRBi);
            CRPr = fmaf(b.z, Rr, CRPr); CRPr = fmaf(-b.w, Ri, CRPr);
            CRPi = fmaf(b.z, Ri, CRPi); CRPi = fmaf( b.w, Rr, CRPi);
        }
        const float wr_ = 1.0f + PRPr, wi_ = PRPi;
        const float invW = 1.0f / fmaf(wr_, wr_, wi_ * wi_);
        const float fr = (PRBr * wr_ + PRBi * wi_) * invW;
        const float fi = (PRBi * wr_ - PRBr * wi_) * invW;
        const float er = CRBr - (CRPr * fr - CRPi * fi);
        const float ei = CRBi - (CRPr * fi + CRPi * fr);
        const float t2 = 2.0f / EPS;
        g_khat[h * LFFT + 1024] = make_float2(t2 * er, t2 * ei);
    }
}

// ============================================================================
// Kernel 2: Hermitian fold + 1024-pt RADIX-4 C2R inverse FFT + store. grid=HH.
// Radix-4 Stockham stage (verified = composition of two radix-2 stages):
//   t0=a+c, t1=a-c, t2=b+d, t3=i(b-d)
//   B[o]=t0+t2; B[o+s]=w^p(t1+t3); B[o+2s]=w^{2p}(t0-t2); B[o+3s]=w^{3p}(t1-t3)
//   p = bi & ~(s-1),  o = bi + 3p,  w = e^{+2*pi*i/1024}
// 5 stages (s = 1,4,16,64,256), 1 butterfly per thread.
// ============================================================================
__global__ void __launch_bounds__(FTH)
fft_kernel(const float* __restrict__ d_in, float* __restrict__ out, int write_d)
{
    __shared__ float2 Kh[LFFT];     // loaded spectrum; reused as FFT pong
    __shared__ float2 Cb[NF];       // folded C2R spectrum / FFT ping
    __shared__ float2 tw4[768];     // e^{+2*pi*i*j/1024}, j < 768

    const int h   = blockIdx.x;
    const int tid = threadIdx.x;

    // vectorized spectrum load (1024 float4s, 4 iters, high MLP)
    {
        const float4* src = (const float4*)(g_khat + h * LFFT);
        float4* dst = (float4*)Kh;
#pragma unroll
        for (int t = 0; t < LFFT / 2 / FTH; t++)
            dst[t * FTH + tid] = src[t * FTH + tid];
    }
    for (int j = tid; j < 768; j += FTH) {
        float s, c;
        sincospif(j * (1.0f / 512.0f), &s, &c);
        tw4[j] = make_float2(c, s);
    }
    __syncthreads();

    // Fold: Re(ifft2048(X)) == ifft1024(C) interleaved as (x[2n], x[2n+1])
    for (int k = tid; k < NF; k += FTH) {
        const float2 P  = Kh[k];
        const float2 Qv = Kh[(2048 - k) & 2047];
        const float2 Rv = Kh[1024 - k];
        const float2 Sv = Kh[1024 + k];
        const float Er = (P.x + Qv.x + Rv.x + Sv.x) * 0.25f;
        const float Ei = (P.y - Qv.y - Rv.y + Sv.y) * 0.25f;
        const float Dr = (P.x + Qv.x - Rv.x - Sv.x) * 0.25f;
        const float Di = (P.y - Qv.y + Rv.y - Sv.y) * 0.25f;
        float st, ct;
        sincospif(k * (1.0f / 1024.0f), &st, &ct);
        const float Or = -st * Dr - ct * Di;
        const float Oi =  ct * Dr - st * Di;
        Cb[k] = make_float2(Er + Or, Ei + Oi);
    }

    // 1024-point radix-4 Stockham inverse FFT: 5 stages, 256 butterflies each
    {
        float2* Abuf = Cb;
        float2* Bbuf = Kh;
#pragma unroll
        for (int s = 1; s <= 256; s *= 4) {
            __syncthreads();
            const int bi    = tid;                // [0, 256)
            const int pbase = bi & ~(s - 1);
            const float2 a = Abuf[bi];
            const float2 b = Abuf[bi + 256];
            const float2 c = Abuf[bi + 512];
            const float2 d = Abuf[bi + 768];
            const float t0r = a.x + c.x, t0i = a.y + c.y;
            const float t1r = a.x - c.x, t1i = a.y - c.y;
            const float t2r = b.x + d.x, t2i = b.y + d.y;
            const float t3r = d.y - b.y, t3i = b.x - d.x;   // i*(b-d)
            const int o = bi + 3 * pbase;
            Bbuf[o] = make_float2(t0r + t2r, t0i + t2i);
            const float2 w1 = tw4[pbase];
            const float2 w2 = tw4[2 * pbase];
            const float2 w3 = tw4[3 * pbase];
            const float u1r = t1r + t3r, u1i = t1i + t3i;
            const float u2r = t0r - t2r, u2i = t0i - t2i;
            const float u3r = t1r - t3r, u3i = t1i - t3i;
            Bbuf[o + s]     = make_float2(u1r * w1.x - u1i * w1.y, u1r * w1.y + u1i * w1.x);
            Bbuf[o + 2 * s] = make_float2(u2r * w2.x - u2i * w2.y, u2r * w2.y + u2i * w2.x);
            Bbuf[o + 3 * s] = make_float2(u3r * w3.x - u3i * w3.y, u3r * w3.y + u3i * w3.x);
            float2* tmp = Abuf; Abuf = Bbuf; Bbuf = tmp;
        }
        __syncthreads();
        // 5 swaps: result is in Abuf (== Kh)

        // c[n] -> (x[2n], x[2n+1]) with 1/1024 scale
        const float sc = 1.0f / (float)NF;
        float2* o2 = (float2*)out;
        for (int n2 = tid; n2 < NF; n2 += FTH) {
            const float2 cv = Abuf[n2];
            o2[h * NF + n2] = make_float2(cv.x * sc, cv.y * sc);
        }
    }

    if (write_d && tid == 0)
        out[HH * LFFT + h] = d_in[h];
}

extern "C" void kernel_launch(void* const* d_in, const int* in_sizes, int n_in,
                              void* d_out, int out_size)
{
    const float* lam_re = (const float*)d_in[0];
    const float* lam_im = (const float*)d_in[1];
    const float* p_re   = (const float*)d_in[2];
    const float* p_im   = (const float*)d_in[3];
    const float* b_re   = (const float*)d_in[4];
    const float* b_im   = (const float*)d_in[5];
    const float* c_re   = (const float*)d_in[6];
    const float* c_im   = (const float*)d_in[7];
    const float* Dv     = (const float*)d_in[8];
    const float* log_dt = (const float*)d_in[9];
    float* out = (float*)d_out;

    const int write_d = (out_size >= HH * LFFT + HH) ? 1 : 0;

    cauchy_kernel<<<HH * NCHUNK, NTH>>>(lam_re, lam_im, p_re, p_im,
                                        b_re, b_im, c_re, c_im, log_dt);
    fft_kernel<<<HH, FTH>>>(Dv, out, write_d);
}

// round 11
// speedup vs baseline: 1.1401x; 1.0004x over previous
#include <cuda_runtime.h>

// Problem constants (fixed by the reference: H=512, N=64, CH=1, L=2048)
#define HH   512
#define NST  64
#define LFFT 2048
#define NF   1024      // half-size complex IFFT length
#define NTH  256       // cauchy block size
#define FTH  256       // fft block size
#define LCHUNK 1024    // l-bins per cauchy block
#define NCHUNK (LFFT / LCHUNK)   // 2 blocks per head
#define JILP 4         // l-bins per thread

typedef unsigned long long ull;

// K_hat scratch: 512 heads x 2048 bins x complex64 = 8 MB (static, no allocation)
__device__ float2 g_khat[HH * LFFT];

__device__ __forceinline__ ull pack2(float a, float b) {
    ull r;
    asm("mov.b64 %0, {%1, %2};" : "=l"(r) : "f"(a), "f"(b));
    return r;
}
__device__ __forceinline__ void unpack2(ull v, float& a, float& b) {
    asm("mov.b64 {%0, %1}, %2;" : "=f"(a), "=f"(b) : "l"(v));
}
__device__ __forceinline__ ull ffma2(ull a, ull b, ull c) {
    ull d;
    asm("fma.rn.f32x2 %0, %1, %2, %3;" : "=l"(d) : "l"(a), "l"(b), "l"(c));
    return d;
}
__device__ __forceinline__ ull fadd2(ull a, ull b) {
    ull d;
    asm("add.rn.f32x2 %0, %1, %2;" : "=l"(d) : "l"(a), "l"(b));
    return d;
}
__device__ __forceinline__ ull fmul2(ull a, ull b) {
    ull d;
    asm("mul.rn.f32x2 %0, %1, %2;" : "=l"(d) : "l"(a), "l"(b));
    return d;
}
__device__ __forceinline__ float frcp(float x) {
    float r;
    asm("rcp.approx.f32 %0, %1;" : "=f"(r) : "f"(x));
    return r;
}

// ============================================================================
// Kernel 1: Cauchy + Woodbury -> K_hat.
// grid = HH * NCHUNK (1024), block = 256, each thread owns JILP=4 bins:
//   l = chunk*1024 + j*256 + tid
// R6-proven accumulation (s2/ds2/q splats), with the reciprocal PREP
// vectorized across j-pairs via f32x2 add/fma/mul (3 fma-ops per 2 bins
// instead of per bin): 34 fma-pipe ops per n instead of 40.
// ============================================================================
__global__ void __launch_bounds__(NTH, 3)
cauchy_kernel(const float* __restrict__ lam_re_in, const float* __restrict__ lam_im_in,
              const float* __restrict__ p_re,  const float* __restrict__ p_im,
              const float* __restrict__ b_re,  const float* __restrict__ b_im,
              const float* __restrict__ c_re,  const float* __restrict__ c_im,
              const float* __restrict__ log_dt)
{
    // Pre-packed f32x2 operand quads per n (64B):
    //   [0] = { (ur*dr, ui*dr),  (ui, -ur) }    u = conj(P)*B
    //   [1] = { (wr*dr, wi*dr),  (wi, -wr) }    w = conj(C)*B
    //   [2] = { (xr*dr, xi*dr),  (xi, -xr) }    x = conj(C)*P
    //   [3] = { (v*dr, -v),      (dr2, -lam) }  v = |P|^2   (note: MINUS lam)
    __shared__ ulonglong2 cst[NST * 4];
    __shared__ float4 rA[NST];      // raw (lam_re, ur, ui, v)  for l==1024 fixup
    __shared__ float4 rB[NST];      // raw (wr, wi, xr, xi)

    const int h     = blockIdx.x / NCHUNK;
    const int chunk = blockIdx.x % NCHUNK;
    const int tid   = threadIdx.x;
    const int lbase = chunk * LCHUNK;

    if (tid < NST) {
        const int idx = h * NST + tid;
        float lr = -log1pf(expf(lam_re_in[idx]));   // Lambda_re = -softplus
        float li = lam_im_in[idx];
        float pr = p_re[idx], pi = p_im[idx];
        float br = b_re[idx], bi = b_im[idx];
        float cr = c_re[idx], ci = c_im[idx];
        float ur = pr * br + pi * bi;
        float ui = pr * bi - pi * br;
        float v  = pr * pr + pi * pi;
        float wr = cr * br + ci * bi;
        float wi = cr * bi - ci * br;
        float xr = cr * pr + ci * pi;
        float xi = cr * pi - ci * pr;
        float dr = -lr;                 // g purely imaginary -> dr l-invariant
        cst[tid * 4 + 0] = make_ulonglong2(pack2(ur * dr, ui * dr), pack2(ui, -ur));
        cst[tid * 4 + 1] = make_ulonglong2(pack2(wr * dr, wi * dr), pack2(wi, -wr));
        cst[tid * 4 + 2] = make_ulonglong2(pack2(xr * dr, xi * dr), pack2(xi, -xr));
        cst[tid * 4 + 3] = make_ulonglong2(pack2(v * dr, -v),       pack2(dr * dr, -li));
        rA[tid] = make_float4(lr, ur, ui, v);
        rB[tid] = make_float4(wr, wi, xr, xi);
    }
    const float tdt = 2.0f * expf(-log_dt[h]);    // 2/dt
    __syncthreads();

    // gi per bin, packed in j-pairs (tau recomputed in the epilogue)
    float giv[JILP];
#pragma unroll
    for (int j = 0; j < JILP; j++) {
        const int l = lbase + j * NTH + tid;
        float sp, cp;
        sincospif(l * (1.0f / 2048.0f), &sp, &cp);   // theta/2 = pi*l/2048
        giv[j] = tdt * __fdividef(sp, cp);           // g = i * (2/dt) tan(theta/2)
    }
    const ull gi01 = pack2(giv[0], giv[1]);
    const ull gi23 = pack2(giv[2], giv[3]);

    ull aU[JILP], aW[JILP], aX[JILP], aV[JILP];
#pragma unroll
    for (int j = 0; j < JILP; j++)
        aU[j] = aW[j] = aX[j] = aV[j] = 0ull;

#pragma unroll 2
    for (int n = 0; n < NST; n++) {
        const ulonglong2 t0 = cst[4 * n + 0];
        const ulonglong2 t1 = cst[4 * n + 1];
        const ulonglong2 t2 = cst[4 * n + 2];
        const ulonglong2 t3 = cst[4 * n + 3];
        float dr2, nlam;
        unpack2(t3.y, dr2, nlam);                 // (dr^2, -lam)
        const ull nlam2 = pack2(nlam, nlam);
        const ull dr22  = pack2(dr2, dr2);

        // ---- pair A: bins j=0,1 ----
        {
            const ull diA  = fadd2(gi01, nlam2);              // (di0, di1)
            const ull denA = ffma2(diA, diA, dr22);           // (den0, den1)
            float den0, den1, di0, di1;
            unpack2(denA, den0, den1);
            unpack2(diA,  di0,  di1);
            const float s0 = frcp(den0);
            const float s1 = frcp(den1);
            const ull dsA = fmul2(pack2(s0, s1), diA);        // (ds0, ds1)
            float ds0, ds1;
            unpack2(dsA, ds0, ds1);
            {
                const ull s2  = pack2(s0, s0);
                const ull ds2 = pack2(ds0, ds0);
                const ull q   = pack2(s0, ds0);
                aU[0] = ffma2(t0.x, s2,  aU[0]); aU[0] = ffma2(t0.y, ds2, aU[0]);
                aW[0] = ffma2(t1.x, s2,  aW[0]); aW[0] = ffma2(t1.y, ds2, aW[0]);
                aX[0] = ffma2(t2.x, s2,  aX[0]); aX[0] = ffma2(t2.y, ds2, aX[0]);
                aV[0] = ffma2(t3.x, q,   aV[0]);
            }
            {
                const ull s2  = pack2(s1, s1);
                const ull ds2 = pack2(ds1, ds1);
                const ull q   = pack2(s1, ds1);
                aU[1] = ffma2(t0.x, s2,  aU[1]); aU[1] = ffma2(t0.y, ds2, aU[1]);
                aW[1] = ffma2(t1.x, s2,  aW[1]); aW[1] = ffma2(t1.y, ds2, aW[1]);
                aX[1] = ffma2(t2.x, s2,  aX[1]); aX[1] = ffma2(t2.y, ds2, aX[1]);
                aV[1] = ffma2(t3.x, q,   aV[1]);
            }
        }
        // ---- pair B: bins j=2,3 ----
        {
            const ull diB  = fadd2(gi23, nlam2);
            const ull denB = ffma2(diB, diB, dr22);
            float den2_, den3_, di2_, di3_;
            unpack2(denB, den2_, den3_);
            unpack2(diB,  di2_,  di3_);
            const float s2_ = frcp(den2_);
            const float s3_ = frcp(den3_);
            const ull dsB = fmul2(pack2(s2_, s3_), diB);
            float ds2_, ds3_;
            unpack2(dsB, ds2_, ds3_);
            {
                const ull s2  = pack2(s2_, s2_);
                const ull ds2 = pack2(ds2_, ds2_);
                const ull q   = pack2(s2_, ds2_);
                aU[2] = ffma2(t0.x, s2,  aU[2]); aU[2] = ffma2(t0.y, ds2, aU[2]);
                aW[2] = ffma2(t1.x, s2,  aW[2]); aW[2] = ffma2(t1.y, ds2, aW[2]);
                aX[2] = ffma2(t2.x, s2,  aX[2]); aX[2] = ffma2(t2.y, ds2, aX[2]);
                aV[2] = ffma2(t3.x, q,   aV[2]);
            }
            {
                const ull s2  = pack2(s3_, s3_);
                const ull ds2 = pack2(ds3_, ds3_);
                const ull q   = pack2(s3_, ds3_);
                aU[3] = ffma2(t0.x, s2,  aU[3]); aU[3] = ffma2(t0.y, ds2, aU[3]);
                aW[3] = ffma2(t1.x, s2,  aW[3]); aW[3] = ffma2(t1.y, ds2, aW[3]);
                aX[3] = ffma2(t2.x, s2,  aX[3]); aX[3] = ffma2(t2.y, ds2, aX[3]);
                aV[3] = ffma2(t3.x, q,   aV[3]);
            }
        }
    }

#pragma unroll
    for (int j = 0; j < JILP; j++) {
        float PRBr, PRBi, CRBr, CRBi, CRPr, CRPi, PRPr, PRPi;
        unpack2(aU[j], PRBr, PRBi);
        unpack2(aW[j], CRBr, CRBi);
        unpack2(aX[j], CRPr, CRPi);
        unpack2(aV[j], PRPr, PRPi);
        const float wr_ = 1.0f + PRPr, wi_ = PRPi;
        const float invW = frcp(fmaf(wr_, wr_, wi_ * wi_));
        const float fr = (PRBr * wr_ + PRBi * wi_) * invW;
        const float fi = (PRBi * wr_ - PRBr * wi_) * invW;
        const float er = CRBr - (CRPr * fr - CRPi * fi);
        const float ei = CRBi - (CRPr * fi + CRPi * fr);
        const int l = lbase + j * NTH + tid;
        // recompute tau in the epilogue (kept out of mainloop registers)
        float sp, cp;
        sincospif(l * (1.0f / 2048.0f), &sp, &cp);
        const float tau = __fdividef(sp, cp);
        // K_hat = (1 + i*tau) * e
        g_khat[h * LFFT + l] = make_float2(er - tau * ei, ei + tau * er);
    }

    // l == 1024 fixup (z = -1, eps-clamped bin) — chunk 1, tid 0 wrote the NaN
    // bin above (j=0), so this overwrite is same-thread ordered.
    if (chunk == 1 && tid == 0) {
        const float EPS = 1.1920929e-7f;
        const float gr = tdt * (2.0f / EPS);   // g real
        float PRBr = 0.f, PRBi = 0.f, PRPr = 0.f, PRPi = 0.f;
        float CRBr = 0.f, CRBi = 0.f, CRPr = 0.f, CRPi = 0.f;
        for (int n = 0; n < NST; n++) {
            const float4 a = rA[n];
            const float4 b = rB[n];
            float dr2_, nlim;
            unpack2(cst[4 * n + 3].y, dr2_, nlim);   // nlim = -lam
            const float dr = gr - a.x;
            const float di = nlim;                   // -lam
            const float rinv = 1.0f / fmaf(dr, dr, di * di);
            const float Rr =  dr * rinv;
            const float Ri = -di * rinv;
            PRBr = fmaf(a.y, Rr, PRBr); PRBr = fmaf(-a.z, Ri, PRBr);
            PRBi = fmaf(a.y, Ri, PRBi); PRBi = fmaf( a.z, Rr, PRBi);
            PRPr = fmaf(a.w, Rr, PRPr);
            PRPi = fmaf(a.w, Ri, PRPi);
            CRBr = fmaf(b.x, Rr, CRBr); CRBr = fmaf(-b.y, Ri, CRBr);
            CRBi = fmaf(b.x, Ri, CRBi); CRBi = fmaf( b.y, Rr, CRBi);
            CRPr = fmaf(b.z, Rr, CRPr); CRPr = fmaf(-b.w, Ri, CRPr);
            CRPi = fmaf(b.z, Ri, CRPi); CRPi = fmaf( b.w, Rr, CRPi);
        }
        const float wr_ = 1.0f + PRPr, wi_ = PRPi;
        const float invW = 1.0f / fmaf(wr_, wr_, wi_ * wi_);
        const float fr = (PRBr * wr_ + PRBi * wi_) * invW;
        const float fi = (PRBi * wr_ - PRBr * wi_) * invW;
        const float er = CRBr - (CRPr * fr - CRPi * fi);
        const float ei = CRBi - (CRPr * fi + CRPi * fr);
        const float t2 = 2.0f / EPS;
        g_khat[h * LFFT + 1024] = make_float2(t2 * er, t2 * ei);
    }
}

// ============================================================================
// Kernel 2 (unchanged, proven 9.9us): Hermitian fold + radix-4 C2R IFFT.
// ============================================================================
__global__ void __launch_bounds__(FTH)
fft_kernel(const float* __restrict__ d_in, float* __restrict__ out, int write_d)
{
    __shared__ float2 Kh[LFFT];     // loaded spectrum; reused as FFT pong
    __shared__ float2 Cb[NF];       // folded C2R spectrum / FFT ping
    __shared__ float2 tw4[768];     // e^{+2*pi*i*j/1024}, j < 768

    const int h   = blockIdx.x;
    const int tid = threadIdx.x;

    {
        const float4* src = (const float4*)(g_khat + h * LFFT);
        float4* dst = (float4*)Kh;
#pragma unroll
        for (int t = 0; t < LFFT / 2 / FTH; t++)
            dst[t * FTH + tid] = src[t * FTH + tid];
    }
    for (int j = tid; j < 768; j += FTH) {
        float s, c;
        sincospif(j * (1.0f / 512.0f), &s, &c);
        tw4[j] = make_float2(c, s);
    }
    __syncthreads();

    for (int k = tid; k < NF; k += FTH) {
        const float2 P  = Kh[k];
        const float2 Qv = Kh[(2048 - k) & 2047];
        const float2 Rv = Kh[1024 - k];
        const float2 Sv = Kh[1024 + k];
        const float Er = (P.x + Qv.x + Rv.x + Sv.x) * 0.25f;
        const float Ei = (P.y - Qv.y - Rv.y + Sv.y) * 0.25f;
        const float Dr = (P.x + Qv.x - Rv.x - Sv.x) * 0.25f;
        const float Di = (P.y - Qv.y + Rv.y - Sv.y) * 0.25f;
        float st, ct;
        sincospif(k * (1.0f / 1024.0f), &st, &ct);
        const float Or = -st * Dr - ct * Di;
        const float Oi =  ct * Dr - st * Di;
        Cb[k] = make_float2(Er + Or, Ei + Oi);
    }

    {
        float2* Abuf = Cb;
        float2* Bbuf = Kh;
#pragma unroll
        for (int s = 1; s <= 256; s *= 4) {
            __syncthreads();
            const int bi    = tid;
            const int pbase = bi & ~(s - 1);
            const float2 a = Abuf[bi];
            const float2 b = Abuf[bi + 256];
            const float2 c = Abuf[bi + 512];
            const float2 d = Abuf[bi + 768];
            const float t0r = a.x + c.x, t0i = a.y + c.y;
            const float t1r = a.x - c.x, t1i = a.y - c.y;
            const float t2r = b.x + d.x, t2i = b.y + d.y;
            const float t3r = d.y - b.y, t3i = b.x - d.x;   // i*(b-d)
            const int o = bi + 3 * pbase;
            Bbuf[o] = make_float2(t0r + t2r, t0i + t2i);
            const float2 w1 = tw4[pbase];
            const float2 w2 = tw4[2 * pbase];
            const float2 w3 = tw4[3 * pbase];
            const float u1r = t1r + t3r, u1i = t1i + t3i;
            const float u2r = t0r - t2r, u2i = t0i - t2i;
            const float u3r = t1r - t3r, u3i = t1i - t3i;
            Bbuf[o + s]     = make_float2(u1r * w1.x - u1i * w1.y, u1r * w1.y + u1i * w1.x);
            Bbuf[o + 2 * s] = make_float2(u2r * w2.x - u2i * w2.y, u2r * w2.y + u2i * w2.x);
            Bbuf[o + 3 * s] = make_float2(u3r * w3.x - u3i * w3.y, u3r * w3.y + u3i * w3.x);
            float2* tmp = Abuf; Abuf = Bbuf; Bbuf = tmp;
        }
        __syncthreads();

        const float sc = 1.0f / (float)NF;
        float2* o2 = (float2*)out;
        for (int n2 = tid; n2 < NF; n2 += FTH) {
            const float2 cv = Abuf[n2];
            o2[h * NF + n2] = make_float2(cv.x * sc, cv.y * sc);
        }
    }

    if (write_d && tid == 0)
        out[HH * LFFT + h] = d_in[h];
}

extern "C" void kernel_launch(void* const* d_in, const int* in_sizes, int n_in,
                              void* d_out, int out_size)
{
    const float* lam_re = (const float*)d_in[0];
    const float* lam_im = (const float*)d_in[1];
    const float* p_re   = (const float*)d_in[2];
    const float* p_im   = (const float*)d_in[3];
    const float* b_re   = (const float*)d_in[4];
    const float* b_im   = (const float*)d_in[5];
    const float* c_re   = (const float*)d_in[6];
    const float* c_im   = (const float*)d_in[7];
    const float* Dv     = (const float*)d_in[8];
    const float* log_dt = (const float*)d_in[9];
    float* out = (float*)d_out;

    const int write_d = (out_size >= HH * LFFT + HH) ? 1 : 0;

    cauchy_kernel<<<HH * NCHUNK, NTH>>>(lam_re, lam_im, p_re, p_im,
                                        b_re, b_im, c_re, c_im, log_dt);
    fft_kernel<<<HH, FTH>>>(Dv, out, write_d);
}